// round 1
// baseline (speedup 1.0000x reference)
#include <cuda_runtime.h>
#include <math.h>
#include <stdint.h>

// ---------------- problem constants ----------------
#define T_TOK 4096          // B*S
#define S_LEN 2048
#define NHEADS 8
#define DIMM 1024
#define QC 128
#define QNOPE 96
#define QROPE 32
#define KVC 128
#define KROPE 64
#define KNOPE 64
#define VHD 256
#define HD 128              // attention qk head dim

// ---------------- scratch (static device globals; no allocation) ----------------
__device__ float g_dq[T_TOK * QC];                       // x @ w_dq + b (pre-norm)
__device__ float g_dkv[T_TOK * (KVC + KROPE)];           // x @ w_dkv_kr + b
__device__ float g_cq[T_TOK * QC];                       // rmsnorm(q latent)
__device__ float g_ckv[T_TOK * KVC];                     // rmsnorm(kv latent)
__device__ float g_krope[T_TOK * KROPE];                 // rope'd k_rope
__device__ float g_qraw[(size_t)T_TOK * 1024];           // cq @ w_uq_qr
__device__ float g_kvraw[(size_t)T_TOK * 2560];          // ckv @ w_uk_uv
__device__ float g_q[(size_t)16 * S_LEN * HD];           // [bh][s][128] q_states
__device__ float g_k[(size_t)16 * S_LEN * HD];           // [bh][s][128] k_states
__device__ float g_v[(size_t)16 * S_LEN * VHD];          // [bh][s][256] v_states
__device__ float g_attn[(size_t)T_TOK * 2048];           // [t][h*256+d]

// ---------------- generic tiled SGEMM: C[M,N] = A[M,K] @ W[K,N] + bias ----------------
// BM=BN=64, BK=16, 256 threads, 4x4 microtile. Requires M%64==0, N%64==0, K%16==0.
__global__ __launch_bounds__(256, 1) void sgemm_bias(
    const float* __restrict__ A, const float* __restrict__ W,
    const float* __restrict__ bias, float* __restrict__ C,
    int M, int N, int K)
{
    __shared__ __align__(16) float As[16][68];   // [k][m], padded
    __shared__ __align__(16) float Bs[16][64];   // [k][n]
    int tid = threadIdx.x;
    int ty = tid >> 4, tx = tid & 15;
    int m0 = blockIdx.y * 64, n0 = blockIdx.x * 64;

    const float* Ab = A + (size_t)m0 * K;
    const float* Wb = W + n0;
    int ar = tid >> 2;            // 0..63 (tile row)
    int ac = (tid & 3) << 2;      // 0,4,8,12 (tile k)
    int wk = tid >> 4;            // 0..15
    int wn = (tid & 15) << 2;     // 0..60

    float acc[4][4] = {};
    for (int k0 = 0; k0 < K; k0 += 16) {
        float4 av = *(const float4*)&Ab[(size_t)ar * K + k0 + ac];
        As[ac + 0][ar] = av.x;
        As[ac + 1][ar] = av.y;
        As[ac + 2][ar] = av.z;
        As[ac + 3][ar] = av.w;
        *(float4*)&Bs[wk][wn] = *(const float4*)&Wb[(size_t)(k0 + wk) * N + wn];
        __syncthreads();
        #pragma unroll
        for (int k = 0; k < 16; k++) {
            float4 a = *(float4*)&As[k][ty * 4];
            float4 b = *(float4*)&Bs[k][tx * 4];
            acc[0][0] = fmaf(a.x, b.x, acc[0][0]); acc[0][1] = fmaf(a.x, b.y, acc[0][1]);
            acc[0][2] = fmaf(a.x, b.z, acc[0][2]); acc[0][3] = fmaf(a.x, b.w, acc[0][3]);
            acc[1][0] = fmaf(a.y, b.x, acc[1][0]); acc[1][1] = fmaf(a.y, b.y, acc[1][1]);
            acc[1][2] = fmaf(a.y, b.z, acc[1][2]); acc[1][3] = fmaf(a.y, b.w, acc[1][3]);
            acc[2][0] = fmaf(a.z, b.x, acc[2][0]); acc[2][1] = fmaf(a.z, b.y, acc[2][1]);
            acc[2][2] = fmaf(a.z, b.z, acc[2][2]); acc[2][3] = fmaf(a.z, b.w, acc[2][3]);
            acc[3][0] = fmaf(a.w, b.x, acc[3][0]); acc[3][1] = fmaf(a.w, b.y, acc[3][1]);
            acc[3][2] = fmaf(a.w, b.z, acc[3][2]); acc[3][3] = fmaf(a.w, b.w, acc[3][3]);
        }
        __syncthreads();
    }
    float4 bv = *(const float4*)&bias[n0 + tx * 4];
    #pragma unroll
    for (int i = 0; i < 4; i++) {
        int row = m0 + ty * 4 + i;
        float4 o;
        o.x = acc[i][0] + bv.x; o.y = acc[i][1] + bv.y;
        o.z = acc[i][2] + bv.z; o.w = acc[i][3] + bv.w;
        *(float4*)&C[(size_t)row * N + n0 + tx * 4] = o;
    }
}

// ---------------- fused RMSNorm (cq, ckv) + K-rope ----------------
__global__ __launch_bounds__(128) void norm_rope_kernel(
    const float* __restrict__ dq, const float* __restrict__ dkv,
    const float* __restrict__ qnw, const float* __restrict__ kvnw,
    const int* __restrict__ pos_ids,
    float* __restrict__ cq, float* __restrict__ ckv, float* __restrict__ kr)
{
    int t = blockIdx.x, tid = threadIdx.x;
    int lane = tid & 31, wid = tid >> 5;
    __shared__ float r1[4], r2[4];
    float v1 = dq[t * 128 + tid];
    float v2 = dkv[t * 192 + tid];
    float s1 = v1 * v1, s2 = v2 * v2;
    #pragma unroll
    for (int o = 16; o; o >>= 1) {
        s1 += __shfl_xor_sync(0xffffffffu, s1, o);
        s2 += __shfl_xor_sync(0xffffffffu, s2, o);
    }
    if (!lane) { r1[wid] = s1; r2[wid] = s2; }
    __syncthreads();
    float t1 = r1[0] + r1[1] + r1[2] + r1[3];
    float t2 = r2[0] + r2[1] + r2[2] + r2[3];
    cq[t * 128 + tid]  = qnw[tid]  * v1 * rsqrtf(t1 * (1.0f / 128.0f) + 1e-8f);
    ckv[t * 128 + tid] = kvnw[tid] * v2 * rsqrtf(t2 * (1.0f / 128.0f) + 1e-8f);
    if (tid < 64) {
        int p = pos_ids[t];
        int i = tid >> 1;
        float invf = (float)exp(-(double)(2 * i) / 64.0 * log(10000.0));
        float ang = (float)p * invf;
        float sn, cs; sincosf(ang, &sn, &cs);
        float xe = dkv[t * 192 + 128 + 2 * i];
        float xo = dkv[t * 192 + 128 + 2 * i + 1];
        kr[t * 64 + tid] = (tid & 1) ? (xe * sn + xo * cs) : (xe * cs - xo * sn);
    }
}

// ---------------- scatter into per-head Q/K/V (with Q rope) ----------------
__global__ __launch_bounds__(256) void scatter_kernel(
    const float* __restrict__ qraw, const float* __restrict__ kvraw,
    const float* __restrict__ kr, const int* __restrict__ pos_ids,
    float* __restrict__ gq, float* __restrict__ gk, float* __restrict__ gv)
{
    int t = blockIdx.x;
    int b = t >> 11, s = t & 2047;
    int tid = threadIdx.x;
    int p = pos_ids[t];
    const float* qrow = qraw + (size_t)t * 1024;
    const float* kvrow = kvraw + (size_t)t * 2560;
    for (int h = 0; h < 8; h++) {
        size_t qk_base = ((size_t)(b * 8 + h) * 2048 + s) * 128;
        size_t v_base  = ((size_t)(b * 8 + h) * 2048 + s) * 256;
        if (tid < 128) {
            int d = tid;
            float val;
            if (d < 96) {
                val = qrow[h * 96 + d];
            } else {
                int j = d - 96, i = j >> 1;
                float invf = (float)exp(-(double)(2 * i) / 32.0 * log(10000.0));
                float ang = (float)p * invf;
                float sn, cs; sincosf(ang, &sn, &cs);
                const float* rb = qrow + 768 + h * 32;
                float xe = rb[2 * i], xo = rb[2 * i + 1];
                val = (j & 1) ? (xe * sn + xo * cs) : (xe * cs - xo * sn);
            }
            gq[qk_base + d] = val;
        } else {
            int d = tid - 128;
            gk[qk_base + d] = (d < 64) ? kvrow[h * 64 + d] : kr[t * 64 + (d - 64)];
        }
        gv[v_base + tid] = kvrow[512 + h * 256 + tid];
    }
}

// ---------------- flash attention: full (non-causal), d=128, v=256 ----------------
// grid (32 q-tiles, 16 bh), 256 threads, BQ=BK=64, online softmax.
#define FA_SMEM_FLOATS (64 * 132 * 2 + 64 * 256 + 64 * 65)
#define FA_SMEM_BYTES (FA_SMEM_FLOATS * 4)

__global__ __launch_bounds__(256, 1) void flash_kernel(
    const float* __restrict__ Q, const float* __restrict__ K,
    const float* __restrict__ V, float* __restrict__ O)
{
    extern __shared__ __align__(16) float sm[];
    float* Qs = sm;               // [64][132]
    float* Ks = sm + 64 * 132;    // [64][132]
    float* Vs = Ks + 64 * 132;    // [64][256]
    float* Ss = Vs + 64 * 256;    // [64][65]
    int bh = blockIdx.y, q0 = blockIdx.x * 64;
    const float* Qg = Q + ((size_t)bh * 2048 + q0) * 128;
    const float* Kg = K + (size_t)bh * 2048 * 128;
    const float* Vg = V + (size_t)bh * 2048 * 256;
    int tid = threadIdx.x, ty = tid >> 4, tx = tid & 15;

    for (int i = tid; i < 2048; i += 256) {
        int r = i >> 5, c = (i & 31) << 2;
        *(float4*)&Qs[r * 132 + c] = *(const float4*)&Qg[r * 128 + c];
    }

    float m_i[4], l_i[4];
    float4 acc[4][4];
    #pragma unroll
    for (int i = 0; i < 4; i++) {
        m_i[i] = -1e30f; l_i[i] = 0.0f;
        #pragma unroll
        for (int j = 0; j < 4; j++) acc[i][j] = make_float4(0.f, 0.f, 0.f, 0.f);
    }
    const float scale = 0.08838834764831845f;  // 1/sqrt(128)

    for (int kc = 0; kc < 32; kc++) {
        __syncthreads();  // previous iteration's readers done
        const float* Kc = Kg + (size_t)kc * 64 * 128;
        for (int i = tid; i < 2048; i += 256) {
            int r = i >> 5, c = (i & 31) << 2;
            *(float4*)&Ks[r * 132 + c] = *(const float4*)&Kc[r * 128 + c];
        }
        const float* Vc = Vg + (size_t)kc * 64 * 256;
        for (int i = tid; i < 4096; i += 256) {
            int r = i >> 6, c = (i & 63) << 2;
            *(float4*)&Vs[r * 256 + c] = *(const float4*)&Vc[r * 256 + c];
        }
        __syncthreads();

        // scores: 64x64 = (16x16 threads) x (4q x 4k)
        float sacc[4][4] = {};
        #pragma unroll 4
        for (int d = 0; d < 128; d += 4) {
            float4 a[4], bb[4];
            #pragma unroll
            for (int i = 0; i < 4; i++) a[i] = *(float4*)&Qs[(ty * 4 + i) * 132 + d];
            #pragma unroll
            for (int j = 0; j < 4; j++) bb[j] = *(float4*)&Ks[(tx * 4 + j) * 132 + d];
            #pragma unroll
            for (int i = 0; i < 4; i++)
                #pragma unroll
                for (int j = 0; j < 4; j++)
                    sacc[i][j] += a[i].x * bb[j].x + a[i].y * bb[j].y
                                + a[i].z * bb[j].z + a[i].w * bb[j].w;
        }
        #pragma unroll
        for (int i = 0; i < 4; i++)
            #pragma unroll
            for (int j = 0; j < 4; j++)
                Ss[(ty * 4 + i) * 65 + tx * 4 + j] = sacc[i][j] * scale;
        __syncthreads();

        // online softmax stats (each thread handles its 4 rows; identical
        // results across the 16 tx threads sharing a row -> deterministic)
        float alpha[4];
        #pragma unroll
        for (int i = 0; i < 4; i++) {
            const float* row = &Ss[(ty * 4 + i) * 65];
            float mc = -1e30f;
            #pragma unroll 8
            for (int k = 0; k < 64; k++) mc = fmaxf(mc, row[k]);
            float mn = fmaxf(m_i[i], mc);
            alpha[i] = __expf(m_i[i] - mn);
            m_i[i] = mn;
        }
        __syncthreads();  // all raw-score reads done before p overwrite
        #pragma unroll
        for (int i = 0; i < 4; i++) {
            float* row = &Ss[(ty * 4 + i) * 65];
            #pragma unroll
            for (int jj = 0; jj < 4; jj++) {
                int k = tx * 4 + jj;
                row[k] = __expf(row[k] - m_i[i]);
            }
        }
        __syncthreads();  // p fully written
        #pragma unroll
        for (int i = 0; i < 4; i++) {
            const float* row = &Ss[(ty * 4 + i) * 65];
            float ls = 0.f;
            #pragma unroll 8
            for (int k = 0; k < 64; k++) ls += row[k];
            l_i[i] = l_i[i] * alpha[i] + ls;
            #pragma unroll
            for (int j = 0; j < 4; j++) {
                acc[i][j].x *= alpha[i]; acc[i][j].y *= alpha[i];
                acc[i][j].z *= alpha[i]; acc[i][j].w *= alpha[i];
            }
        }

        // PV: O[64][256] += P[64][64] @ V[64][256]; thread covers 4 rows x (4 j-blocks of f4)
        #pragma unroll 2
        for (int k = 0; k < 64; k++) {
            float pr[4];
            #pragma unroll
            for (int i = 0; i < 4; i++) pr[i] = Ss[(ty * 4 + i) * 65 + k];
            float4 vv[4];
            #pragma unroll
            for (int j = 0; j < 4; j++) vv[j] = *(float4*)&Vs[k * 256 + j * 64 + tx * 4];
            #pragma unroll
            for (int i = 0; i < 4; i++)
                #pragma unroll
                for (int j = 0; j < 4; j++) {
                    acc[i][j].x = fmaf(pr[i], vv[j].x, acc[i][j].x);
                    acc[i][j].y = fmaf(pr[i], vv[j].y, acc[i][j].y);
                    acc[i][j].z = fmaf(pr[i], vv[j].z, acc[i][j].z);
                    acc[i][j].w = fmaf(pr[i], vv[j].w, acc[i][j].w);
                }
        }
    }

    // epilogue: write [t][h*256 + d]
    int b = bh >> 3, h = bh & 7;
    #pragma unroll
    for (int i = 0; i < 4; i++) {
        int row = q0 + ty * 4 + i;
        size_t base = ((size_t)(b * 2048 + row)) * 2048 + h * 256;
        float inv = 1.0f / l_i[i];
        #pragma unroll
        for (int j = 0; j < 4; j++) {
            float4 o;
            o.x = acc[i][j].x * inv; o.y = acc[i][j].y * inv;
            o.z = acc[i][j].z * inv; o.w = acc[i][j].w * inv;
            *(float4*)&O[base + j * 64 + tx * 4] = o;
        }
    }
}

// ---------------- launch ----------------
extern "C" void kernel_launch(void* const* d_in, const int* in_sizes, int n_in,
                              void* d_out, int out_size)
{
    const float* x         = (const float*)d_in[0];
    const int*   pos       = (const int*)d_in[1];
    const float* w_dq_w    = (const float*)d_in[2];
    const float* w_dq_b    = (const float*)d_in[3];
    const float* q_norm_w  = (const float*)d_in[4];
    const float* w_uq_qr_w = (const float*)d_in[5];
    const float* w_uq_qr_b = (const float*)d_in[6];
    const float* w_dkv_w   = (const float*)d_in[7];
    const float* w_dkv_b   = (const float*)d_in[8];
    const float* kv_norm_w = (const float*)d_in[9];
    const float* w_uk_w    = (const float*)d_in[10];
    const float* w_uk_b    = (const float*)d_in[11];
    const float* w_o_w     = (const float*)d_in[12];
    const float* w_o_b     = (const float*)d_in[13];
    float* out = (float*)d_out;

    float *dq, *dkv, *cq, *ckv, *kr, *qraw, *kvraw, *gq, *gk, *gv, *gattn;
    cudaGetSymbolAddress((void**)&dq, g_dq);
    cudaGetSymbolAddress((void**)&dkv, g_dkv);
    cudaGetSymbolAddress((void**)&cq, g_cq);
    cudaGetSymbolAddress((void**)&ckv, g_ckv);
    cudaGetSymbolAddress((void**)&kr, g_krope);
    cudaGetSymbolAddress((void**)&qraw, g_qraw);
    cudaGetSymbolAddress((void**)&kvraw, g_kvraw);
    cudaGetSymbolAddress((void**)&gq, g_q);
    cudaGetSymbolAddress((void**)&gk, g_k);
    cudaGetSymbolAddress((void**)&gv, g_v);
    cudaGetSymbolAddress((void**)&gattn, g_attn);

    cudaFuncSetAttribute(flash_kernel, cudaFuncAttributeMaxDynamicSharedMemorySize,
                         FA_SMEM_BYTES);

    // down projections
    sgemm_bias<<<dim3(QC / 64, T_TOK / 64), 256>>>(x, w_dq_w, w_dq_b, dq,
                                                   T_TOK, QC, DIMM);
    sgemm_bias<<<dim3((KVC + KROPE) / 64, T_TOK / 64), 256>>>(x, w_dkv_w, w_dkv_b, dkv,
                                                              T_TOK, KVC + KROPE, DIMM);
    // rmsnorm + k rope
    norm_rope_kernel<<<T_TOK, 128>>>(dq, dkv, q_norm_w, kv_norm_w, pos, cq, ckv, kr);
    // up projections
    sgemm_bias<<<dim3(1024 / 64, T_TOK / 64), 256>>>(cq, w_uq_qr_w, w_uq_qr_b, qraw,
                                                     T_TOK, 1024, QC);
    sgemm_bias<<<dim3(2560 / 64, T_TOK / 64), 256>>>(ckv, w_uk_w, w_uk_b, kvraw,
                                                     T_TOK, 2560, KVC);
    // build per-head states (q rope applied here)
    scatter_kernel<<<T_TOK, 256>>>(qraw, kvraw, kr, pos, gq, gk, gv);
    // attention
    flash_kernel<<<dim3(S_LEN / 64, 16), 256, FA_SMEM_BYTES>>>(gq, gk, gv, gattn);
    // output projection
    sgemm_bias<<<dim3(DIMM / 64, T_TOK / 64), 256>>>(gattn, w_o_w, w_o_b, out,
                                                     T_TOK, DIMM, 2048);
}

// round 2
// speedup vs baseline: 2.5757x; 2.5757x over previous
#include <cuda_runtime.h>
#include <math.h>
#include <stdint.h>

// ---------------- problem constants ----------------
#define T_TOK 4096          // B*S
#define S_LEN 2048
#define NHEADS 8
#define DIMM 1024
#define QC 128
#define QROPE 32
#define KVC 128
#define KROPE 64
#define VHD 256
#define HD 128

// ---------------- scratch ----------------
__device__ float g_dq[T_TOK * QC];
__device__ float g_dkv[T_TOK * (KVC + KROPE)];
__device__ float g_cq[T_TOK * QC];
__device__ float g_ckv[T_TOK * KVC];
__device__ float g_krope[T_TOK * KROPE];
__device__ float g_qraw[(size_t)T_TOK * 1024];
__device__ float g_kvraw[(size_t)T_TOK * 2560];
__device__ float g_q[(size_t)16 * S_LEN * HD];
__device__ float g_k[(size_t)16 * S_LEN * HD];
__device__ float g_v[(size_t)16 * S_LEN * VHD];
__device__ float g_attn[(size_t)T_TOK * 2048];

// ---------------- tf32 helpers ----------------
__device__ __forceinline__ float f2tf(float f) {
    uint32_t u;
    asm("cvt.rna.tf32.f32 %0, %1;" : "=r"(u) : "f"(f));
    return __uint_as_float(u);
}

__device__ __forceinline__ void mma_tf32(float c[4], const uint32_t a[4], const uint32_t b[2]) {
    asm volatile(
        "mma.sync.aligned.m16n8k8.row.col.f32.tf32.tf32.f32 "
        "{%0,%1,%2,%3},{%4,%5,%6,%7},{%8,%9},{%0,%1,%2,%3};"
        : "+f"(c[0]), "+f"(c[1]), "+f"(c[2]), "+f"(c[3])
        : "r"(a[0]), "r"(a[1]), "r"(a[2]), "r"(a[3]), "r"(b[0]), "r"(b[1]));
}

// ---------------- tensor-core SGEMM: C[M,N] = A[M,K] @ W[K,N] + bias ----------------
// block tile 128x64, BK=16, 256 threads (8 warps, 4x2), warp tile 32x32.
__global__ __launch_bounds__(256) void sgemm_tc(
    const float* __restrict__ A, const float* __restrict__ W,
    const float* __restrict__ bias, float* __restrict__ C,
    int M, int N, int K)
{
    __shared__ float As[128][20];   // [m][k], pad->20 (bank map 20g+t conflict-free)
    __shared__ float Bs[16][72];    // [k][n], pad->72 (bank map 8t+g conflict-free)
    int tid = threadIdx.x, lane = tid & 31, w = tid >> 5;
    int g = lane >> 2, t = lane & 3;
    int wm = (w >> 1) * 32, wn = (w & 1) * 32;
    int m0 = blockIdx.y * 128, n0 = blockIdx.x * 64;

    float c[2][4][4] = {};

    int ar = tid >> 1;                 // A load: row 0..127
    int acb = (tid & 1) * 8;           // col base 0 or 8
    int bk = tid >> 4;                 // B load: k 0..15
    int bc = (tid & 15) * 4;           // n col

    for (int k0 = 0; k0 < K; k0 += 16) {
        float4 v1 = *(const float4*)&A[(size_t)(m0 + ar) * K + k0 + acb];
        float4 v2 = *(const float4*)&A[(size_t)(m0 + ar) * K + k0 + acb + 4];
        As[ar][acb + 0] = f2tf(v1.x); As[ar][acb + 1] = f2tf(v1.y);
        As[ar][acb + 2] = f2tf(v1.z); As[ar][acb + 3] = f2tf(v1.w);
        As[ar][acb + 4] = f2tf(v2.x); As[ar][acb + 5] = f2tf(v2.y);
        As[ar][acb + 6] = f2tf(v2.z); As[ar][acb + 7] = f2tf(v2.w);
        float4 bv = *(const float4*)&W[(size_t)(k0 + bk) * N + n0 + bc];
        Bs[bk][bc + 0] = f2tf(bv.x); Bs[bk][bc + 1] = f2tf(bv.y);
        Bs[bk][bc + 2] = f2tf(bv.z); Bs[bk][bc + 3] = f2tf(bv.w);
        __syncthreads();

        #pragma unroll
        for (int ks = 0; ks < 16; ks += 8) {
            uint32_t a[2][4], b[4][2];
            #pragma unroll
            for (int i = 0; i < 2; i++) {
                int mr = wm + i * 16;
                a[i][0] = __float_as_uint(As[mr + g][ks + t]);
                a[i][1] = __float_as_uint(As[mr + g + 8][ks + t]);
                a[i][2] = __float_as_uint(As[mr + g][ks + t + 4]);
                a[i][3] = __float_as_uint(As[mr + g + 8][ks + t + 4]);
            }
            #pragma unroll
            for (int j = 0; j < 4; j++) {
                b[j][0] = __float_as_uint(Bs[ks + t][wn + j * 8 + g]);
                b[j][1] = __float_as_uint(Bs[ks + t + 4][wn + j * 8 + g]);
            }
            #pragma unroll
            for (int i = 0; i < 2; i++)
                #pragma unroll
                for (int j = 0; j < 4; j++)
                    mma_tf32(c[i][j], a[i], b[j]);
        }
        __syncthreads();
    }

    #pragma unroll
    for (int i = 0; i < 2; i++) {
        #pragma unroll
        for (int j = 0; j < 4; j++) {
            int row = m0 + wm + i * 16 + g;
            int col = n0 + wn + j * 8 + 2 * t;
            float2 bb = *(const float2*)&bias[col];
            float2 o0 = { c[i][j][0] + bb.x, c[i][j][1] + bb.y };
            float2 o1 = { c[i][j][2] + bb.x, c[i][j][3] + bb.y };
            *(float2*)&C[(size_t)row * N + col] = o0;
            *(float2*)&C[(size_t)(row + 8) * N + col] = o1;
        }
    }
}

// ---------------- fused RMSNorm + K-rope ----------------
__global__ __launch_bounds__(128) void norm_rope_kernel(
    const float* __restrict__ dq, const float* __restrict__ dkv,
    const float* __restrict__ qnw, const float* __restrict__ kvnw,
    const int* __restrict__ pos_ids,
    float* __restrict__ cq, float* __restrict__ ckv, float* __restrict__ kr)
{
    int t = blockIdx.x, tid = threadIdx.x;
    int lane = tid & 31, wid = tid >> 5;
    __shared__ float r1[4], r2[4];
    float v1 = dq[t * 128 + tid];
    float v2 = dkv[t * 192 + tid];
    float s1 = v1 * v1, s2 = v2 * v2;
    #pragma unroll
    for (int o = 16; o; o >>= 1) {
        s1 += __shfl_xor_sync(0xffffffffu, s1, o);
        s2 += __shfl_xor_sync(0xffffffffu, s2, o);
    }
    if (!lane) { r1[wid] = s1; r2[wid] = s2; }
    __syncthreads();
    float t1 = r1[0] + r1[1] + r1[2] + r1[3];
    float t2 = r2[0] + r2[1] + r2[2] + r2[3];
    cq[t * 128 + tid]  = qnw[tid]  * v1 * rsqrtf(t1 * (1.0f / 128.0f) + 1e-8f);
    ckv[t * 128 + tid] = kvnw[tid] * v2 * rsqrtf(t2 * (1.0f / 128.0f) + 1e-8f);
    if (tid < 64) {
        int p = pos_ids[t];
        int i = tid >> 1;
        float invf = (float)exp(-(double)(2 * i) / 64.0 * log(10000.0));
        float ang = (float)p * invf;
        float sn, cs; sincosf(ang, &sn, &cs);
        float xe = dkv[t * 192 + 128 + 2 * i];
        float xo = dkv[t * 192 + 128 + 2 * i + 1];
        kr[t * 64 + tid] = (tid & 1) ? (xe * sn + xo * cs) : (xe * cs - xo * sn);
    }
}

// ---------------- scatter into per-head Q/K/V (with Q rope) ----------------
__global__ __launch_bounds__(256) void scatter_kernel(
    const float* __restrict__ qraw, const float* __restrict__ kvraw,
    const float* __restrict__ kr, const int* __restrict__ pos_ids,
    float* __restrict__ gq, float* __restrict__ gk, float* __restrict__ gv)
{
    int t = blockIdx.x;
    int b = t >> 11, s = t & 2047;
    int tid = threadIdx.x;
    int p = pos_ids[t];
    const float* qrow = qraw + (size_t)t * 1024;
    const float* kvrow = kvraw + (size_t)t * 2560;
    for (int h = 0; h < 8; h++) {
        size_t qk_base = ((size_t)(b * 8 + h) * 2048 + s) * 128;
        size_t v_base  = ((size_t)(b * 8 + h) * 2048 + s) * 256;
        if (tid < 128) {
            int d = tid;
            float val;
            if (d < 96) {
                val = qrow[h * 96 + d];
            } else {
                int j = d - 96, i = j >> 1;
                float invf = (float)exp(-(double)(2 * i) / 32.0 * log(10000.0));
                float ang = (float)p * invf;
                float sn, cs; sincosf(ang, &sn, &cs);
                const float* rb = qrow + 768 + h * 32;
                float xe = rb[2 * i], xo = rb[2 * i + 1];
                val = (j & 1) ? (xe * sn + xo * cs) : (xe * cs - xo * sn);
            }
            gq[qk_base + d] = val;
        } else {
            int d = tid - 128;
            gk[qk_base + d] = (d < 64) ? kvrow[h * 64 + d] : kr[t * 64 + (d - 64)];
        }
        gv[v_base + tid] = kvrow[512 + h * 256 + tid];
    }
}

// ---------------- tensor-core flash attention ----------------
// BQ=BK=64, d=128, v=256. 256 threads (8 warps).
// scores: warps 2x4 -> warp tile 32x16. PV: warps 4x2 -> warp tile 16x128.
#define FAF_Q   (64 * 132)
#define FAF_K   (64 * 132)
#define FAF_V   (64 * 264)
#define FAF_S   (64 * 68)
#define FA2_FLOATS (FAF_Q + FAF_K + FAF_V + FAF_S + 192)
#define FA2_BYTES  (FA2_FLOATS * 4)

__global__ __launch_bounds__(256, 1) void flash_tc(
    const float* __restrict__ Q, const float* __restrict__ K,
    const float* __restrict__ V, float* __restrict__ O)
{
    extern __shared__ __align__(16) float sm[];
    float* Qs = sm;                      // [64][132]
    float* Ks = Qs + FAF_Q;              // [64][132]
    float* Vs = Ks + FAF_K;              // [64][264]
    float* Ss = Vs + FAF_V;              // [64][68]
    float* msm = Ss + FAF_S;             // [64]
    float* lsm = msm + 64;               // [64]
    float* alsm = lsm + 64;              // [64]

    int bh = blockIdx.y, q0 = blockIdx.x * 64;
    const float* Qg = Q + ((size_t)bh * 2048 + q0) * 128;
    const float* Kg = K + (size_t)bh * 2048 * 128;
    const float* Vg = V + (size_t)bh * 2048 * 256;
    int tid = threadIdx.x, lane = tid & 31, w = tid >> 5;
    int g = lane >> 2, t = lane & 3;

    // score-phase warp coords (2x4)
    int sw_m = (w >> 2) * 32, sw_n = (w & 3) * 16;
    // pv-phase warp coords (4x2)
    int pv_m = (w >> 1) * 16, pv_n = (w & 1) * 128;

    // load Q (tf32-converted)
    for (int i = tid; i < 2048; i += 256) {
        int r = i >> 5, c = (i & 31) << 2;
        float4 v = *(const float4*)&Qg[r * 128 + c];
        Qs[r * 132 + c + 0] = f2tf(v.x); Qs[r * 132 + c + 1] = f2tf(v.y);
        Qs[r * 132 + c + 2] = f2tf(v.z); Qs[r * 132 + c + 3] = f2tf(v.w);
    }
    if (tid < 64) { msm[tid] = -1e30f; lsm[tid] = 0.0f; }

    float o[16][4] = {};
    const float scale = 0.08838834764831845f;  // 1/sqrt(128)

    for (int kc = 0; kc < 32; kc++) {
        __syncthreads();
        const float* Kc = Kg + (size_t)kc * 64 * 128;
        for (int i = tid; i < 2048; i += 256) {
            int r = i >> 5, c = (i & 31) << 2;
            float4 v = *(const float4*)&Kc[r * 128 + c];
            Ks[r * 132 + c + 0] = f2tf(v.x); Ks[r * 132 + c + 1] = f2tf(v.y);
            Ks[r * 132 + c + 2] = f2tf(v.z); Ks[r * 132 + c + 3] = f2tf(v.w);
        }
        const float* Vc = Vg + (size_t)kc * 64 * 256;
        for (int i = tid; i < 4096; i += 256) {
            int r = i >> 6, c = (i & 63) << 2;
            float4 v = *(const float4*)&Vc[r * 256 + c];
            Vs[r * 264 + c + 0] = f2tf(v.x); Vs[r * 264 + c + 1] = f2tf(v.y);
            Vs[r * 264 + c + 2] = f2tf(v.z); Vs[r * 264 + c + 3] = f2tf(v.w);
        }
        __syncthreads();

        // ---- scores: S = Q @ K^T (warp tile 32x16) ----
        float sc[2][2][4] = {};
        #pragma unroll 4
        for (int d = 0; d < 128; d += 8) {
            uint32_t a[2][4], b[2][2];
            #pragma unroll
            for (int i = 0; i < 2; i++) {
                int mr = sw_m + i * 16;
                a[i][0] = __float_as_uint(Qs[(mr + g) * 132 + d + t]);
                a[i][1] = __float_as_uint(Qs[(mr + g + 8) * 132 + d + t]);
                a[i][2] = __float_as_uint(Qs[(mr + g) * 132 + d + t + 4]);
                a[i][3] = __float_as_uint(Qs[(mr + g + 8) * 132 + d + t + 4]);
            }
            #pragma unroll
            for (int j = 0; j < 2; j++) {
                int nr = sw_n + j * 8;
                b[j][0] = __float_as_uint(Ks[(nr + g) * 132 + d + t]);
                b[j][1] = __float_as_uint(Ks[(nr + g) * 132 + d + t + 4]);
            }
            #pragma unroll
            for (int i = 0; i < 2; i++)
                #pragma unroll
                for (int j = 0; j < 2; j++)
                    mma_tf32(sc[i][j], a[i], b[j]);
        }
        #pragma unroll
        for (int i = 0; i < 2; i++)
            #pragma unroll
            for (int j = 0; j < 2; j++) {
                int r0 = sw_m + i * 16 + g;
                int c0 = sw_n + j * 8 + 2 * t;
                float2 s0 = { sc[i][j][0] * scale, sc[i][j][1] * scale };
                float2 s1 = { sc[i][j][2] * scale, sc[i][j][3] * scale };
                *(float2*)&Ss[r0 * 68 + c0] = s0;
                *(float2*)&Ss[(r0 + 8) * 68 + c0] = s1;
            }
        __syncthreads();

        // ---- online softmax: warp w handles rows w*8..w*8+7 ----
        {
            int rl = lane >> 2, q = lane & 3;
            int r = w * 8 + rl;
            float* row = &Ss[r * 68];
            float mc = -1e30f;
            #pragma unroll
            for (int cix = 0; cix < 16; cix++) mc = fmaxf(mc, row[q * 16 + cix]);
            mc = fmaxf(mc, __shfl_xor_sync(0xffffffffu, mc, 1));
            mc = fmaxf(mc, __shfl_xor_sync(0xffffffffu, mc, 2));
            float mold = msm[r];
            float mn = fmaxf(mold, mc);
            float al = __expf(mold - mn);
            float ls = 0.0f;
            #pragma unroll
            for (int cix = 0; cix < 16; cix++) {
                float p = __expf(row[q * 16 + cix] - mn);
                ls += p;
                row[q * 16 + cix] = f2tf(p);
            }
            ls += __shfl_xor_sync(0xffffffffu, ls, 1);
            ls += __shfl_xor_sync(0xffffffffu, ls, 2);
            if (q == 0) {
                msm[r] = mn;
                lsm[r] = lsm[r] * al + ls;
                alsm[r] = al;
            }
        }
        __syncthreads();

        // ---- PV: O += P @ V (warp tile 16x128) ----
        float aA = alsm[pv_m + g];
        float aB = alsm[pv_m + g + 8];
        #pragma unroll
        for (int j = 0; j < 16; j++) {
            o[j][0] *= aA; o[j][1] *= aA;
            o[j][2] *= aB; o[j][3] *= aB;
        }
        #pragma unroll 2
        for (int ks = 0; ks < 64; ks += 8) {
            uint32_t a[4];
            a[0] = __float_as_uint(Ss[(pv_m + g) * 68 + ks + t]);
            a[1] = __float_as_uint(Ss[(pv_m + g + 8) * 68 + ks + t]);
            a[2] = __float_as_uint(Ss[(pv_m + g) * 68 + ks + t + 4]);
            a[3] = __float_as_uint(Ss[(pv_m + g + 8) * 68 + ks + t + 4]);
            #pragma unroll
            for (int j = 0; j < 16; j++) {
                uint32_t b[2];
                b[0] = __float_as_uint(Vs[(ks + t) * 264 + pv_n + j * 8 + g]);
                b[1] = __float_as_uint(Vs[(ks + t + 4) * 264 + pv_n + j * 8 + g]);
                mma_tf32(o[j], a, b);
            }
        }
    }

    // epilogue
    int b = bh >> 3, h = bh & 7;
    float invA = 1.0f / lsm[pv_m + g];
    float invB = 1.0f / lsm[pv_m + g + 8];
    int rowA = q0 + pv_m + g;
    int rowB = rowA + 8;
    #pragma unroll
    for (int j = 0; j < 16; j++) {
        int col = h * 256 + pv_n + j * 8 + 2 * t;
        float2 oA = { o[j][0] * invA, o[j][1] * invA };
        float2 oB = { o[j][2] * invB, o[j][3] * invB };
        *(float2*)&O[((size_t)(b * 2048 + rowA)) * 2048 + col] = oA;
        *(float2*)&O[((size_t)(b * 2048 + rowB)) * 2048 + col] = oB;
    }
}

// ---------------- launch ----------------
extern "C" void kernel_launch(void* const* d_in, const int* in_sizes, int n_in,
                              void* d_out, int out_size)
{
    const float* x         = (const float*)d_in[0];
    const int*   pos       = (const int*)d_in[1];
    const float* w_dq_w    = (const float*)d_in[2];
    const float* w_dq_b    = (const float*)d_in[3];
    const float* q_norm_w  = (const float*)d_in[4];
    const float* w_uq_qr_w = (const float*)d_in[5];
    const float* w_uq_qr_b = (const float*)d_in[6];
    const float* w_dkv_w   = (const float*)d_in[7];
    const float* w_dkv_b   = (const float*)d_in[8];
    const float* kv_norm_w = (const float*)d_in[9];
    const float* w_uk_w    = (const float*)d_in[10];
    const float* w_uk_b    = (const float*)d_in[11];
    const float* w_o_w     = (const float*)d_in[12];
    const float* w_o_b     = (const float*)d_in[13];
    float* out = (float*)d_out;

    float *dq, *dkv, *cq, *ckv, *kr, *qraw, *kvraw, *gq, *gk, *gv, *gattn;
    cudaGetSymbolAddress((void**)&dq, g_dq);
    cudaGetSymbolAddress((void**)&dkv, g_dkv);
    cudaGetSymbolAddress((void**)&cq, g_cq);
    cudaGetSymbolAddress((void**)&ckv, g_ckv);
    cudaGetSymbolAddress((void**)&kr, g_krope);
    cudaGetSymbolAddress((void**)&qraw, g_qraw);
    cudaGetSymbolAddress((void**)&kvraw, g_kvraw);
    cudaGetSymbolAddress((void**)&gq, g_q);
    cudaGetSymbolAddress((void**)&gk, g_k);
    cudaGetSymbolAddress((void**)&gv, g_v);
    cudaGetSymbolAddress((void**)&gattn, g_attn);

    cudaFuncSetAttribute(flash_tc, cudaFuncAttributeMaxDynamicSharedMemorySize,
                         FA2_BYTES);

    // down projections
    sgemm_tc<<<dim3(QC / 64, T_TOK / 128), 256>>>(x, w_dq_w, w_dq_b, dq,
                                                  T_TOK, QC, DIMM);
    sgemm_tc<<<dim3((KVC + KROPE) / 64, T_TOK / 128), 256>>>(x, w_dkv_w, w_dkv_b, dkv,
                                                             T_TOK, KVC + KROPE, DIMM);
    // rmsnorm + k rope
    norm_rope_kernel<<<T_TOK, 128>>>(dq, dkv, q_norm_w, kv_norm_w, pos, cq, ckv, kr);
    // up projections
    sgemm_tc<<<dim3(1024 / 64, T_TOK / 128), 256>>>(cq, w_uq_qr_w, w_uq_qr_b, qraw,
                                                    T_TOK, 1024, QC);
    sgemm_tc<<<dim3(2560 / 64, T_TOK / 128), 256>>>(ckv, w_uk_w, w_uk_b, kvraw,
                                                    T_TOK, 2560, KVC);
    // build per-head states
    scatter_kernel<<<T_TOK, 256>>>(qraw, kvraw, kr, pos, gq, gk, gv);
    // attention
    flash_tc<<<dim3(S_LEN / 64, 16), 256, FA2_BYTES>>>(gq, gk, gv, gattn);
    // output projection
    sgemm_tc<<<dim3(DIMM / 64, T_TOK / 128), 256>>>(gattn, w_o_w, w_o_b, out,
                                                    T_TOK, DIMM, 2048);
}

// round 3
// speedup vs baseline: 3.5118x; 1.3634x over previous
#include <cuda_runtime.h>
#include <math.h>
#include <stdint.h>

// ---------------- problem constants ----------------
#define T_TOK 4096
#define S_LEN 2048
#define DIMM 1024
#define QC 128
#define KVC 128
#define KROPE 64
#define VHD 256
#define HD 128

// ---------------- scratch ----------------
__device__ float g_dq[T_TOK * QC];
__device__ float g_dkv[T_TOK * (KVC + KROPE)];
__device__ float g_cq[T_TOK * QC];
__device__ float g_ckv[T_TOK * KVC];
__device__ float g_krope[T_TOK * KROPE];
__device__ float g_qraw[(size_t)T_TOK * 1024];
__device__ float g_kvraw[(size_t)T_TOK * 2560];
__device__ float g_q[(size_t)16 * S_LEN * HD];
__device__ float g_k[(size_t)16 * S_LEN * HD];
__device__ float g_v[(size_t)16 * S_LEN * VHD];
__device__ float g_attn[(size_t)T_TOK * 2048];

// ---------------- helpers ----------------
__device__ __forceinline__ float f2tf(float f) {
    uint32_t u;
    asm("cvt.rna.tf32.f32 %0, %1;" : "=r"(u) : "f"(f));
    return __uint_as_float(u);
}
__device__ __forceinline__ uint32_t f2tfu(float f) {
    uint32_t u;
    asm("cvt.rna.tf32.f32 %0, %1;" : "=r"(u) : "f"(f));
    return u;
}

__device__ __forceinline__ void mma_tf32(float c[4], const uint32_t a[4], const uint32_t b[2]) {
    asm volatile(
        "mma.sync.aligned.m16n8k8.row.col.f32.tf32.tf32.f32 "
        "{%0,%1,%2,%3},{%4,%5,%6,%7},{%8,%9},{%0,%1,%2,%3};"
        : "+f"(c[0]), "+f"(c[1]), "+f"(c[2]), "+f"(c[3])
        : "r"(a[0]), "r"(a[1]), "r"(a[2]), "r"(a[3]), "r"(b[0]), "r"(b[1]));
}

__device__ __forceinline__ void cp_async16(void* smem_dst, const void* gsrc) {
    uint32_t s = (uint32_t)__cvta_generic_to_shared(smem_dst);
    asm volatile("cp.async.ca.shared.global [%0], [%1], 16;\n" :: "r"(s), "l"(gsrc));
}
#define CP_COMMIT() asm volatile("cp.async.commit_group;\n" ::: "memory")
#define CP_WAIT1()  asm volatile("cp.async.wait_group 1;\n" ::: "memory")

// ---------------- double-buffered tf32 tensor-core GEMM ----------------
// C[M,N] = A[M,K] @ W[K,N] + bias.  Block tile 128 x BN, BK=16, 256 thr, 8 warps.
// Warp tile 32 x (BN/2).  M%128==0, N%BN==0, K%16==0.
template<int BN>
__global__ __launch_bounds__(256) void sgemm_db(
    const float* __restrict__ A, const float* __restrict__ W,
    const float* __restrict__ bias, float* __restrict__ C,
    int M, int N, int K)
{
    constexpr int BM = 128, BK = 16;
    constexpr int LDA = BK + 4;       // 20: banks (20g+t) distinct
    constexpr int LDB = BN + 8;       // banks (8t+g) distinct
    constexpr int NJ = BN / 16;       // 8-wide j tiles per warp
    constexpr int RB = BN / 64;       // float4 B-loads per thread
    __shared__ float As[2][BM][LDA];
    __shared__ float Bs[2][BK][LDB];

    int tid = threadIdx.x, lane = tid & 31, w = tid >> 5;
    int g = lane >> 2, t = lane & 3;
    int wm = (w >> 1) * 32, wn = (w & 1) * (BN / 2);
    int m0 = blockIdx.y * BM, n0 = blockIdx.x * BN;

    int ar = tid >> 1, ac = (tid & 1) * 8;   // A: 128 rows x 16 cols
    int br = tid >> 4, bc = (tid & 15) * (4 * RB);

    const float* Ag = A + (size_t)(m0 + ar) * K + ac;
    const float* Wg = W + (size_t)br * N + n0 + bc;

    float c[2][NJ][4] = {};
    float4 ra0, ra1, rb[RB];

    auto gload = [&](int k0) {
        ra0 = *(const float4*)(Ag + k0);
        ra1 = *(const float4*)(Ag + k0 + 4);
        #pragma unroll
        for (int r = 0; r < RB; r++)
            rb[r] = *(const float4*)(Wg + (size_t)k0 * N + r * 4);
    };
    auto sstore = [&](int buf) {
        As[buf][ar][ac + 0] = f2tf(ra0.x); As[buf][ar][ac + 1] = f2tf(ra0.y);
        As[buf][ar][ac + 2] = f2tf(ra0.z); As[buf][ar][ac + 3] = f2tf(ra0.w);
        As[buf][ar][ac + 4] = f2tf(ra1.x); As[buf][ar][ac + 5] = f2tf(ra1.y);
        As[buf][ar][ac + 6] = f2tf(ra1.z); As[buf][ar][ac + 7] = f2tf(ra1.w);
        #pragma unroll
        for (int r = 0; r < RB; r++) {
            Bs[buf][br][bc + r * 4 + 0] = f2tf(rb[r].x);
            Bs[buf][br][bc + r * 4 + 1] = f2tf(rb[r].y);
            Bs[buf][br][bc + r * 4 + 2] = f2tf(rb[r].z);
            Bs[buf][br][bc + r * 4 + 3] = f2tf(rb[r].w);
        }
    };

    gload(0);
    sstore(0);
    __syncthreads();

    int nt = K / BK;
    for (int it = 0; it < nt; it++) {
        int cur = it & 1;
        if (it + 1 < nt) gload((it + 1) * BK);
        #pragma unroll
        for (int ks = 0; ks < 16; ks += 8) {
            uint32_t a[2][4], b[NJ][2];
            #pragma unroll
            for (int i = 0; i < 2; i++) {
                int mr = wm + i * 16;
                a[i][0] = __float_as_uint(As[cur][mr + g][ks + t]);
                a[i][1] = __float_as_uint(As[cur][mr + g + 8][ks + t]);
                a[i][2] = __float_as_uint(As[cur][mr + g][ks + t + 4]);
                a[i][3] = __float_as_uint(As[cur][mr + g + 8][ks + t + 4]);
            }
            #pragma unroll
            for (int j = 0; j < NJ; j++) {
                b[j][0] = __float_as_uint(Bs[cur][ks + t][wn + j * 8 + g]);
                b[j][1] = __float_as_uint(Bs[cur][ks + t + 4][wn + j * 8 + g]);
            }
            #pragma unroll
            for (int i = 0; i < 2; i++)
                #pragma unroll
                for (int j = 0; j < NJ; j++)
                    mma_tf32(c[i][j], a[i], b[j]);
        }
        if (it + 1 < nt) sstore(cur ^ 1);
        __syncthreads();
    }

    #pragma unroll
    for (int i = 0; i < 2; i++) {
        #pragma unroll
        for (int j = 0; j < NJ; j++) {
            int row = m0 + wm + i * 16 + g;
            int col = n0 + wn + j * 8 + 2 * t;
            float2 bb = *(const float2*)&bias[col];
            float2 o0 = { c[i][j][0] + bb.x, c[i][j][1] + bb.y };
            float2 o1 = { c[i][j][2] + bb.x, c[i][j][3] + bb.y };
            *(float2*)&C[(size_t)row * N + col] = o0;
            *(float2*)&C[(size_t)(row + 8) * N + col] = o1;
        }
    }
}

// ---------------- fused RMSNorm + K-rope ----------------
__global__ __launch_bounds__(128) void norm_rope_kernel(
    const float* __restrict__ dq, const float* __restrict__ dkv,
    const float* __restrict__ qnw, const float* __restrict__ kvnw,
    const int* __restrict__ pos_ids,
    float* __restrict__ cq, float* __restrict__ ckv, float* __restrict__ kr)
{
    int t = blockIdx.x, tid = threadIdx.x;
    int lane = tid & 31, wid = tid >> 5;
    __shared__ float r1[4], r2[4];
    float v1 = dq[t * 128 + tid];
    float v2 = dkv[t * 192 + tid];
    float s1 = v1 * v1, s2 = v2 * v2;
    #pragma unroll
    for (int o = 16; o; o >>= 1) {
        s1 += __shfl_xor_sync(0xffffffffu, s1, o);
        s2 += __shfl_xor_sync(0xffffffffu, s2, o);
    }
    if (!lane) { r1[wid] = s1; r2[wid] = s2; }
    __syncthreads();
    float t1 = r1[0] + r1[1] + r1[2] + r1[3];
    float t2 = r2[0] + r2[1] + r2[2] + r2[3];
    cq[t * 128 + tid]  = qnw[tid]  * v1 * rsqrtf(t1 * (1.0f / 128.0f) + 1e-8f);
    ckv[t * 128 + tid] = kvnw[tid] * v2 * rsqrtf(t2 * (1.0f / 128.0f) + 1e-8f);
    if (tid < 64) {
        int p = pos_ids[t];
        int i = tid >> 1;
        float invf = (float)exp(-(double)(2 * i) / 64.0 * log(10000.0));
        float ang = (float)p * invf;
        float sn, cs; sincosf(ang, &sn, &cs);
        float xe = dkv[t * 192 + 128 + 2 * i];
        float xo = dkv[t * 192 + 128 + 2 * i + 1];
        kr[t * 64 + tid] = (tid & 1) ? (xe * sn + xo * cs) : (xe * cs - xo * sn);
    }
}

// ---------------- scatter into per-head Q/K/V (with Q rope) ----------------
__global__ __launch_bounds__(256) void scatter_kernel(
    const float* __restrict__ qraw, const float* __restrict__ kvraw,
    const float* __restrict__ kr, const int* __restrict__ pos_ids,
    float* __restrict__ gq, float* __restrict__ gk, float* __restrict__ gv)
{
    int t = blockIdx.x;
    int b = t >> 11, s = t & 2047;
    int tid = threadIdx.x;
    int p = pos_ids[t];
    const float* qrow = qraw + (size_t)t * 1024;
    const float* kvrow = kvraw + (size_t)t * 2560;
    for (int h = 0; h < 8; h++) {
        size_t qk_base = ((size_t)(b * 8 + h) * 2048 + s) * 128;
        size_t v_base  = ((size_t)(b * 8 + h) * 2048 + s) * 256;
        if (tid < 128) {
            int d = tid;
            float val;
            if (d < 96) {
                val = qrow[h * 96 + d];
            } else {
                int j = d - 96, i = j >> 1;
                float invf = (float)exp(-(double)(2 * i) / 32.0 * log(10000.0));
                float ang = (float)p * invf;
                float sn, cs; sincosf(ang, &sn, &cs);
                const float* rb = qrow + 768 + h * 32;
                float xe = rb[2 * i], xo = rb[2 * i + 1];
                val = (j & 1) ? (xe * sn + xo * cs) : (xe * cs - xo * sn);
            }
            gq[qk_base + d] = val;
        } else {
            int d = tid - 128;
            gk[qk_base + d] = (d < 64) ? kvrow[h * 64 + d] : kr[t * 64 + (d - 64)];
        }
        gv[v_base + tid] = kvrow[512 + h * 256 + tid];
    }
}

// ---------------- cp.async-pipelined tensor-core flash attention ----------------
// BQ=BK=64, d=128, v=256, 256 threads (8 warps), online softmax.
#define FAF_Q   (64 * 132)
#define FAF_K   (64 * 132)
#define FAF_V   (64 * 264)
#define FAF_S   (64 * 68)
#define FA2_FLOATS (FAF_Q + FAF_K + FAF_V + FAF_S + 192)
#define FA2_BYTES  (FA2_FLOATS * 4)

__global__ __launch_bounds__(256, 1) void flash_tc(
    const float* __restrict__ Q, const float* __restrict__ K,
    const float* __restrict__ V, float* __restrict__ O)
{
    extern __shared__ __align__(16) float sm[];
    float* Qs = sm;                      // [64][132] (tf32-converted)
    float* Ks = Qs + FAF_Q;              // [64][132] (raw f32; cvt at use)
    float* Vs = Ks + FAF_K;              // [64][264] (raw f32; cvt at use)
    float* Ss = Vs + FAF_V;              // [64][68]  (P, tf32-converted)
    float* msm = Ss + FAF_S;
    float* lsm = msm + 64;
    float* alsm = lsm + 64;

    int bh = blockIdx.y, q0 = blockIdx.x * 64;
    const float* Qg = Q + ((size_t)bh * 2048 + q0) * 128;
    const float* Kg = K + (size_t)bh * 2048 * 128;
    const float* Vg = V + (size_t)bh * 2048 * 256;
    int tid = threadIdx.x, lane = tid & 31, w = tid >> 5;
    int g = lane >> 2, t = lane & 3;

    int sw_m = (w >> 2) * 32, sw_n = (w & 3) * 16;   // score warps 2x4
    int pv_m = (w >> 1) * 16, pv_n = (w & 1) * 128;  // pv warps 4x2

    auto loadK = [&](int kc) {
        const float* Kc = Kg + (size_t)kc * 64 * 128;
        #pragma unroll
        for (int i = tid; i < 2048; i += 256) {
            int r = i >> 5, c = (i & 31) << 2;
            cp_async16(&Ks[r * 132 + c], &Kc[r * 128 + c]);
        }
    };
    auto loadV = [&](int kc) {
        const float* Vc = Vg + (size_t)kc * 64 * 256;
        #pragma unroll
        for (int i = tid; i < 4096; i += 256) {
            int r = i >> 6, c = (i & 63) << 2;
            cp_async16(&Vs[r * 264 + c], &Vc[r * 256 + c]);
        }
    };

    // prologue: Q (converted), async K0/V0
    for (int i = tid; i < 2048; i += 256) {
        int r = i >> 5, c = (i & 31) << 2;
        float4 v = *(const float4*)&Qg[r * 128 + c];
        Qs[r * 132 + c + 0] = f2tf(v.x); Qs[r * 132 + c + 1] = f2tf(v.y);
        Qs[r * 132 + c + 2] = f2tf(v.z); Qs[r * 132 + c + 3] = f2tf(v.w);
    }
    if (tid < 64) { msm[tid] = -1e30f; lsm[tid] = 0.0f; }
    loadK(0); CP_COMMIT();
    loadV(0); CP_COMMIT();

    float o[16][4] = {};
    const float scale = 0.08838834764831845f;  // 1/sqrt(128)

    for (int kc = 0; kc < 32; kc++) {
        CP_WAIT1();              // K(kc) landed (V(kc) may still be in flight)
        __syncthreads();

        // ---- scores: S = Q @ K^T (warp tile 32x16) ----
        float sc[2][2][4] = {};
        #pragma unroll 4
        for (int d = 0; d < 128; d += 8) {
            uint32_t a[2][4], b[2][2];
            #pragma unroll
            for (int i = 0; i < 2; i++) {
                int mr = sw_m + i * 16;
                a[i][0] = __float_as_uint(Qs[(mr + g) * 132 + d + t]);
                a[i][1] = __float_as_uint(Qs[(mr + g + 8) * 132 + d + t]);
                a[i][2] = __float_as_uint(Qs[(mr + g) * 132 + d + t + 4]);
                a[i][3] = __float_as_uint(Qs[(mr + g + 8) * 132 + d + t + 4]);
            }
            #pragma unroll
            for (int j = 0; j < 2; j++) {
                int nr = sw_n + j * 8;
                b[j][0] = f2tfu(Ks[(nr + g) * 132 + d + t]);
                b[j][1] = f2tfu(Ks[(nr + g) * 132 + d + t + 4]);
            }
            #pragma unroll
            for (int i = 0; i < 2; i++)
                #pragma unroll
                for (int j = 0; j < 2; j++)
                    mma_tf32(sc[i][j], a[i], b[j]);
        }
        #pragma unroll
        for (int i = 0; i < 2; i++)
            #pragma unroll
            for (int j = 0; j < 2; j++) {
                int r0 = sw_m + i * 16 + g;
                int c0 = sw_n + j * 8 + 2 * t;
                float2 s0 = { sc[i][j][0] * scale, sc[i][j][1] * scale };
                float2 s1 = { sc[i][j][2] * scale, sc[i][j][3] * scale };
                *(float2*)&Ss[r0 * 68 + c0] = s0;
                *(float2*)&Ss[(r0 + 8) * 68 + c0] = s1;
            }
        __syncthreads();       // scores in smem; Ks free

        if (kc + 1 < 32) loadK(kc + 1);
        CP_COMMIT();           // keep group cadence even when empty

        // ---- online softmax: warp w handles rows w*8..w*8+7 ----
        {
            int rl = lane >> 2, q = lane & 3;
            int r = w * 8 + rl;
            float* row = &Ss[r * 68];
            float mc = -1e30f;
            #pragma unroll
            for (int cix = 0; cix < 16; cix++) mc = fmaxf(mc, row[q * 16 + cix]);
            mc = fmaxf(mc, __shfl_xor_sync(0xffffffffu, mc, 1));
            mc = fmaxf(mc, __shfl_xor_sync(0xffffffffu, mc, 2));
            float mold = msm[r];
            float mn = fmaxf(mold, mc);
            float al = __expf(mold - mn);
            float ls = 0.0f;
            #pragma unroll
            for (int cix = 0; cix < 16; cix++) {
                float p = __expf(row[q * 16 + cix] - mn);
                ls += p;
                row[q * 16 + cix] = f2tf(p);
            }
            ls += __shfl_xor_sync(0xffffffffu, ls, 1);
            ls += __shfl_xor_sync(0xffffffffu, ls, 2);
            if (q == 0) {
                msm[r] = mn;
                lsm[r] = lsm[r] * al + ls;
                alsm[r] = al;
            }
        }
        CP_WAIT1();            // V(kc) landed (K(kc+1) may still be in flight)
        __syncthreads();

        // ---- PV: O += P @ V (warp tile 16x128) ----
        float aA = alsm[pv_m + g];
        float aB = alsm[pv_m + g + 8];
        #pragma unroll
        for (int j = 0; j < 16; j++) {
            o[j][0] *= aA; o[j][1] *= aA;
            o[j][2] *= aB; o[j][3] *= aB;
        }
        #pragma unroll 2
        for (int ks = 0; ks < 64; ks += 8) {
            uint32_t a[4];
            a[0] = __float_as_uint(Ss[(pv_m + g) * 68 + ks + t]);
            a[1] = __float_as_uint(Ss[(pv_m + g + 8) * 68 + ks + t]);
            a[2] = __float_as_uint(Ss[(pv_m + g) * 68 + ks + t + 4]);
            a[3] = __float_as_uint(Ss[(pv_m + g + 8) * 68 + ks + t + 4]);
            #pragma unroll
            for (int j = 0; j < 16; j++) {
                uint32_t b[2];
                b[0] = f2tfu(Vs[(ks + t) * 264 + pv_n + j * 8 + g]);
                b[1] = f2tfu(Vs[(ks + t + 4) * 264 + pv_n + j * 8 + g]);
                mma_tf32(o[j], a, b);
            }
        }
        __syncthreads();       // Vs free
        if (kc + 1 < 32) loadV(kc + 1);
        CP_COMMIT();
    }

    // epilogue
    int b = bh >> 3, h = bh & 7;
    float invA = 1.0f / lsm[pv_m + g];
    float invB = 1.0f / lsm[pv_m + g + 8];
    int rowA = q0 + pv_m + g;
    int rowB = rowA + 8;
    #pragma unroll
    for (int j = 0; j < 16; j++) {
        int col = h * 256 + pv_n + j * 8 + 2 * t;
        float2 oA = { o[j][0] * invA, o[j][1] * invA };
        float2 oB = { o[j][2] * invB, o[j][3] * invB };
        *(float2*)&O[((size_t)(b * 2048 + rowA)) * 2048 + col] = oA;
        *(float2*)&O[((size_t)(b * 2048 + rowB)) * 2048 + col] = oB;
    }
}

// ---------------- launch ----------------
extern "C" void kernel_launch(void* const* d_in, const int* in_sizes, int n_in,
                              void* d_out, int out_size)
{
    const float* x         = (const float*)d_in[0];
    const int*   pos       = (const int*)d_in[1];
    const float* w_dq_w    = (const float*)d_in[2];
    const float* w_dq_b    = (const float*)d_in[3];
    const float* q_norm_w  = (const float*)d_in[4];
    const float* w_uq_qr_w = (const float*)d_in[5];
    const float* w_uq_qr_b = (const float*)d_in[6];
    const float* w_dkv_w   = (const float*)d_in[7];
    const float* w_dkv_b   = (const float*)d_in[8];
    const float* kv_norm_w = (const float*)d_in[9];
    const float* w_uk_w    = (const float*)d_in[10];
    const float* w_uk_b    = (const float*)d_in[11];
    const float* w_o_w     = (const float*)d_in[12];
    const float* w_o_b     = (const float*)d_in[13];
    float* out = (float*)d_out;

    float *dq, *dkv, *cq, *ckv, *kr, *qraw, *kvraw, *gq, *gk, *gv, *gattn;
    cudaGetSymbolAddress((void**)&dq, g_dq);
    cudaGetSymbolAddress((void**)&dkv, g_dkv);
    cudaGetSymbolAddress((void**)&cq, g_cq);
    cudaGetSymbolAddress((void**)&ckv, g_ckv);
    cudaGetSymbolAddress((void**)&kr, g_krope);
    cudaGetSymbolAddress((void**)&qraw, g_qraw);
    cudaGetSymbolAddress((void**)&kvraw, g_kvraw);
    cudaGetSymbolAddress((void**)&gq, g_q);
    cudaGetSymbolAddress((void**)&gk, g_k);
    cudaGetSymbolAddress((void**)&gv, g_v);
    cudaGetSymbolAddress((void**)&gattn, g_attn);

    cudaFuncSetAttribute(flash_tc, cudaFuncAttributeMaxDynamicSharedMemorySize,
                         FA2_BYTES);

    // down projections
    sgemm_db<128><<<dim3(1, 32), 256>>>(x, w_dq_w, w_dq_b, dq, T_TOK, QC, DIMM);
    sgemm_db<64><<<dim3(3, 32), 256>>>(x, w_dkv_w, w_dkv_b, dkv,
                                       T_TOK, KVC + KROPE, DIMM);
    // rmsnorm + k rope
    norm_rope_kernel<<<T_TOK, 128>>>(dq, dkv, q_norm_w, kv_norm_w, pos, cq, ckv, kr);
    // up projections
    sgemm_db<128><<<dim3(8, 32), 256>>>(cq, w_uq_qr_w, w_uq_qr_b, qraw,
                                        T_TOK, 1024, QC);
    sgemm_db<128><<<dim3(20, 32), 256>>>(ckv, w_uk_w, w_uk_b, kvraw,
                                         T_TOK, 2560, KVC);
    // build per-head states
    scatter_kernel<<<T_TOK, 256>>>(qraw, kvraw, kr, pos, gq, gk, gv);
    // attention
    flash_tc<<<dim3(S_LEN / 64, 16), 256, FA2_BYTES>>>(gq, gk, gv, gattn);
    // output projection
    sgemm_db<128><<<dim3(8, 32), 256>>>(gattn, w_o_w, w_o_b, out,
                                        T_TOK, DIMM, 2048);
}

// round 5
// speedup vs baseline: 3.9891x; 1.1359x over previous
#include <cuda_runtime.h>
#include <math.h>
#include <stdint.h>

// ---------------- problem constants ----------------
#define T_TOK 4096
#define S_LEN 2048
#define DIMM 1024
#define QC 128
#define KVC 128
#define KROPE 64
#define VHD 256
#define HD 128

// ---------------- scratch ----------------
__device__ float g_dq[T_TOK * QC];
__device__ float g_dkv[T_TOK * (KVC + KROPE)];
__device__ float g_cq[T_TOK * QC];
__device__ float g_ckv[T_TOK * KVC];
__device__ float g_krope[T_TOK * KROPE];
__device__ float g_qraw[(size_t)T_TOK * 1024];
__device__ float g_kvraw[(size_t)T_TOK * 2560];
__device__ float g_q[(size_t)16 * S_LEN * HD];     // [bh][s][128] tf32
__device__ float g_k[(size_t)16 * S_LEN * HD];     // [bh][s][128] tf32
__device__ float g_vt[(size_t)16 * VHD * S_LEN];   // [bh][n][s]  tf32 (V^T)
__device__ float g_attn[(size_t)T_TOK * 2048];

// ---------------- helpers ----------------
__device__ __forceinline__ float f2tf(float f) {
    uint32_t u;
    asm("cvt.rna.tf32.f32 %0, %1;" : "=r"(u) : "f"(f));
    return __uint_as_float(u);
}

__device__ __forceinline__ void mma_tf32(float c[4], const uint32_t a[4], const uint32_t b[2]) {
    asm volatile(
        "mma.sync.aligned.m16n8k8.row.col.f32.tf32.tf32.f32 "
        "{%0,%1,%2,%3},{%4,%5,%6,%7},{%8,%9},{%0,%1,%2,%3};"
        : "+f"(c[0]), "+f"(c[1]), "+f"(c[2]), "+f"(c[3])
        : "r"(a[0]), "r"(a[1]), "r"(a[2]), "r"(a[3]), "r"(b[0]), "r"(b[1]));
}

__device__ __forceinline__ void ldsm4(uint32_t r[4], uint32_t saddr) {
    asm volatile("ldmatrix.sync.aligned.m8n8.x4.shared.b16 {%0,%1,%2,%3}, [%4];"
        : "=r"(r[0]), "=r"(r[1]), "=r"(r[2]), "=r"(r[3]) : "r"(saddr));
}

__device__ __forceinline__ void cp_async16(void* smem_dst, const void* gsrc) {
    uint32_t s = (uint32_t)__cvta_generic_to_shared(smem_dst);
    asm volatile("cp.async.ca.shared.global [%0], [%1], 16;\n" :: "r"(s), "l"(gsrc));
}
#define CP_COMMIT() asm volatile("cp.async.commit_group;\n" ::: "memory")
#define CP_WAIT1()  asm volatile("cp.async.wait_group 1;\n" ::: "memory")

// ---------------- double-buffered tf32 tensor-core GEMM (unchanged) ----------------
template<int BN>
__global__ __launch_bounds__(256) void sgemm_db(
    const float* __restrict__ A, const float* __restrict__ W,
    const float* __restrict__ bias, float* __restrict__ C,
    int M, int N, int K)
{
    constexpr int BM = 128, BK = 16;
    constexpr int LDA = BK + 4;
    constexpr int LDB = BN + 8;
    constexpr int NJ = BN / 16;
    constexpr int RB = BN / 64;
    __shared__ float As[2][BM][LDA];
    __shared__ float Bs[2][BK][LDB];

    int tid = threadIdx.x, lane = tid & 31, w = tid >> 5;
    int g = lane >> 2, t = lane & 3;
    int wm = (w >> 1) * 32, wn = (w & 1) * (BN / 2);
    int m0 = blockIdx.y * BM, n0 = blockIdx.x * BN;

    int ar = tid >> 1, ac = (tid & 1) * 8;
    int br = tid >> 4, bc = (tid & 15) * (4 * RB);

    const float* Ag = A + (size_t)(m0 + ar) * K + ac;
    const float* Wg = W + (size_t)br * N + n0 + bc;

    float c[2][NJ][4] = {};
    float4 ra0, ra1, rb[RB];

    auto gload = [&](int k0) {
        ra0 = *(const float4*)(Ag + k0);
        ra1 = *(const float4*)(Ag + k0 + 4);
        #pragma unroll
        for (int r = 0; r < RB; r++)
            rb[r] = *(const float4*)(Wg + (size_t)k0 * N + r * 4);
    };
    auto sstore = [&](int buf) {
        As[buf][ar][ac + 0] = f2tf(ra0.x); As[buf][ar][ac + 1] = f2tf(ra0.y);
        As[buf][ar][ac + 2] = f2tf(ra0.z); As[buf][ar][ac + 3] = f2tf(ra0.w);
        As[buf][ar][ac + 4] = f2tf(ra1.x); As[buf][ar][ac + 5] = f2tf(ra1.y);
        As[buf][ar][ac + 6] = f2tf(ra1.z); As[buf][ar][ac + 7] = f2tf(ra1.w);
        #pragma unroll
        for (int r = 0; r < RB; r++) {
            Bs[buf][br][bc + r * 4 + 0] = f2tf(rb[r].x);
            Bs[buf][br][bc + r * 4 + 1] = f2tf(rb[r].y);
            Bs[buf][br][bc + r * 4 + 2] = f2tf(rb[r].z);
            Bs[buf][br][bc + r * 4 + 3] = f2tf(rb[r].w);
        }
    };

    gload(0);
    sstore(0);
    __syncthreads();

    int nt = K / BK;
    for (int it = 0; it < nt; it++) {
        int cur = it & 1;
        if (it + 1 < nt) gload((it + 1) * BK);
        #pragma unroll
        for (int ks = 0; ks < 16; ks += 8) {
            uint32_t a[2][4], b[NJ][2];
            #pragma unroll
            for (int i = 0; i < 2; i++) {
                int mr = wm + i * 16;
                a[i][0] = __float_as_uint(As[cur][mr + g][ks + t]);
                a[i][1] = __float_as_uint(As[cur][mr + g + 8][ks + t]);
                a[i][2] = __float_as_uint(As[cur][mr + g][ks + t + 4]);
                a[i][3] = __float_as_uint(As[cur][mr + g + 8][ks + t + 4]);
            }
            #pragma unroll
            for (int j = 0; j < NJ; j++) {
                b[j][0] = __float_as_uint(Bs[cur][ks + t][wn + j * 8 + g]);
                b[j][1] = __float_as_uint(Bs[cur][ks + t + 4][wn + j * 8 + g]);
            }
            #pragma unroll
            for (int i = 0; i < 2; i++)
                #pragma unroll
                for (int j = 0; j < NJ; j++)
                    mma_tf32(c[i][j], a[i], b[j]);
        }
        if (it + 1 < nt) sstore(cur ^ 1);
        __syncthreads();
    }

    #pragma unroll
    for (int i = 0; i < 2; i++) {
        #pragma unroll
        for (int j = 0; j < NJ; j++) {
            int row = m0 + wm + i * 16 + g;
            int col = n0 + wn + j * 8 + 2 * t;
            float2 bb = *(const float2*)&bias[col];
            float2 o0 = { c[i][j][0] + bb.x, c[i][j][1] + bb.y };
            float2 o1 = { c[i][j][2] + bb.x, c[i][j][3] + bb.y };
            *(float2*)&C[(size_t)row * N + col] = o0;
            *(float2*)&C[(size_t)(row + 8) * N + col] = o1;
        }
    }
}

// ---------------- fused RMSNorm + K-rope ----------------
__global__ __launch_bounds__(128) void norm_rope_kernel(
    const float* __restrict__ dq, const float* __restrict__ dkv,
    const float* __restrict__ qnw, const float* __restrict__ kvnw,
    const int* __restrict__ pos_ids,
    float* __restrict__ cq, float* __restrict__ ckv, float* __restrict__ kr)
{
    int t = blockIdx.x, tid = threadIdx.x;
    int lane = tid & 31, wid = tid >> 5;
    __shared__ float r1[4], r2[4];
    float v1 = dq[t * 128 + tid];
    float v2 = dkv[t * 192 + tid];
    float s1 = v1 * v1, s2 = v2 * v2;
    #pragma unroll
    for (int o = 16; o; o >>= 1) {
        s1 += __shfl_xor_sync(0xffffffffu, s1, o);
        s2 += __shfl_xor_sync(0xffffffffu, s2, o);
    }
    if (!lane) { r1[wid] = s1; r2[wid] = s2; }
    __syncthreads();
    float t1 = r1[0] + r1[1] + r1[2] + r1[3];
    float t2 = r2[0] + r2[1] + r2[2] + r2[3];
    cq[t * 128 + tid]  = qnw[tid]  * v1 * rsqrtf(t1 * (1.0f / 128.0f) + 1e-8f);
    ckv[t * 128 + tid] = kvnw[tid] * v2 * rsqrtf(t2 * (1.0f / 128.0f) + 1e-8f);
    if (tid < 64) {
        int p = pos_ids[t];
        int i = tid >> 1;
        float invf = (float)exp(-(double)(2 * i) / 64.0 * log(10000.0));
        float ang = (float)p * invf;
        float sn, cs; sincosf(ang, &sn, &cs);
        float xe = dkv[t * 192 + 128 + 2 * i];
        float xo = dkv[t * 192 + 128 + 2 * i + 1];
        kr[t * 64 + tid] = (tid & 1) ? (xe * sn + xo * cs) : (xe * cs - xo * sn);
    }
}

// ---------------- scatter Q/K (tf32-converted) ----------------
__global__ __launch_bounds__(256) void scatter_qk(
    const float* __restrict__ qraw, const float* __restrict__ kvraw,
    const float* __restrict__ kr, const int* __restrict__ pos_ids,
    float* __restrict__ gq, float* __restrict__ gk)
{
    int t = blockIdx.x;
    int b = t >> 11, s = t & 2047;
    int tid = threadIdx.x;
    int p = pos_ids[t];
    const float* qrow = qraw + (size_t)t * 1024;
    const float* kvrow = kvraw + (size_t)t * 2560;
    for (int h = 0; h < 8; h++) {
        size_t qk_base = ((size_t)(b * 8 + h) * 2048 + s) * 128;
        if (tid < 128) {
            int d = tid;
            float val;
            if (d < 96) {
                val = qrow[h * 96 + d];
            } else {
                int j = d - 96, i = j >> 1;
                float invf = (float)exp(-(double)(2 * i) / 32.0 * log(10000.0));
                float ang = (float)p * invf;
                float sn, cs; sincosf(ang, &sn, &cs);
                const float* rb = qrow + 768 + h * 32;
                float xe = rb[2 * i], xo = rb[2 * i + 1];
                val = (j & 1) ? (xe * sn + xo * cs) : (xe * cs - xo * sn);
            }
            gq[qk_base + d] = f2tf(val);
        } else {
            int d = tid - 128;
            float val = (d < 64) ? kvrow[h * 64 + d] : kr[t * 64 + (d - 64)];
            gk[qk_base + d] = f2tf(val);
        }
    }
}

// ---------------- V transpose: kvraw V part -> gvt[bh][n][s] (tf32) ----------------
__global__ __launch_bounds__(256) void v_transpose(
    const float* __restrict__ kvraw, float* __restrict__ gvt)
{
    __shared__ float ts[32][33];
    int bh = blockIdx.x;
    int s0 = blockIdx.y * 32, n0 = blockIdx.z * 32;
    int b = bh >> 3, h = bh & 7;
    int c = threadIdx.x & 31, r0 = threadIdx.x >> 5;
    #pragma unroll
    for (int rr = r0; rr < 32; rr += 8)
        ts[rr][c] = kvraw[(size_t)(b * 2048 + s0 + rr) * 2560 + 512 + h * 256 + n0 + c];
    __syncthreads();
    #pragma unroll
    for (int rr = r0; rr < 32; rr += 8)
        gvt[(size_t)(bh * 256 + n0 + rr) * 2048 + s0 + c] = f2tf(ts[c][rr]);
}

// ---------------- LDSM tensor-core flash attention ----------------
// BQ=128, BK=64, d=128, v=256, 512 threads (16 warps), online softmax.
#define FQ_F (128 * 132)
#define FK_F (64 * 132)
#define FV_F (256 * 68)
#define FS_F (128 * 68)
#define FA3_FLOATS (FQ_F + FK_F + FV_F + FS_F + 384)
#define FA3_BYTES  (FA3_FLOATS * 4)

__global__ __launch_bounds__(512, 1) void flash_tc(
    const float* __restrict__ Q, const float* __restrict__ K,
    const float* __restrict__ VT, float* __restrict__ O)
{
    extern __shared__ __align__(16) float sm[];
    float* Qs = sm;                 // [128][132] tf32
    float* Ks = Qs + FQ_F;          // [64][132]  tf32
    float* Vs = Ks + FK_F;          // [256][68]  tf32 (V^T: [n][k])
    float* Ss = Vs + FV_F;          // [128][68]  tf32 P
    float* msm = Ss + FS_F;         // [128]
    float* lsm = msm + 128;
    float* alsm = lsm + 128;

    int bh = blockIdx.y, q0 = blockIdx.x * 128;
    const float* Qg = Q + ((size_t)bh * 2048 + q0) * 128;
    const float* Kg = K + (size_t)bh * 2048 * 128;
    const float* Vg = VT + (size_t)bh * 256 * 2048;
    int tid = threadIdx.x, lane = tid & 31, w = tid >> 5;
    int g = lane >> 2, t = lane & 3;

    // ldmatrix per-lane offsets
    int laneA_row = ((lane >> 3) & 1) * 8 + (lane & 7);
    int laneA_col = (lane >> 4) * 4;
    int laneB_row = (lane >> 4) * 8 + (lane & 7);
    int laneB_col = ((lane >> 3) & 1) * 4;

    // score warps 4x4: tile 32(m) x 16(n). pv warps 4x4: tile 32(m) x 64(n)
    int sw_m = (w >> 2) * 32, sw_n = (w & 3) * 16;
    int pv_m = (w >> 2) * 32, pv_n = (w & 3) * 64;

    uint32_t qA = (uint32_t)__cvta_generic_to_shared(
        &Qs[(sw_m + laneA_row) * 132 + laneA_col]);
    uint32_t kB = (uint32_t)__cvta_generic_to_shared(
        &Ks[(sw_n + laneB_row) * 132 + laneB_col]);
    uint32_t pA = (uint32_t)__cvta_generic_to_shared(
        &Ss[(pv_m + laneA_row) * 68 + laneA_col]);
    uint32_t vB = (uint32_t)__cvta_generic_to_shared(
        &Vs[(pv_n + laneB_row) * 68 + laneB_col]);

    auto loadK = [&](int kc) {
        const float* Kc = Kg + (size_t)kc * 64 * 128;
        #pragma unroll
        for (int i = tid; i < 2048; i += 512) {
            int r = i >> 5, c = (i & 31) << 2;
            cp_async16(&Ks[r * 132 + c], &Kc[r * 128 + c]);
        }
    };
    auto loadV = [&](int kc) {
        #pragma unroll
        for (int i = tid; i < 4096; i += 512) {
            int r = i >> 4, c = (i & 15) << 2;
            cp_async16(&Vs[r * 68 + c], &Vg[(size_t)r * 2048 + kc * 64 + c]);
        }
    };

    // prologue
    for (int i = tid; i < 4096; i += 512) {
        int r = i >> 5, c = (i & 31) << 2;
        *(float4*)&Qs[r * 132 + c] = *(const float4*)&Qg[r * 128 + c];
    }
    if (tid < 128) { msm[tid] = -1e30f; lsm[tid] = 0.0f; }
    loadK(0); CP_COMMIT();
    loadV(0); CP_COMMIT();

    float oc[2][8][4] = {};
    const float scale = 0.08838834764831845f;  // 1/sqrt(128)

    for (int kc = 0; kc < 32; kc++) {
        CP_WAIT1();
        __syncthreads();

        // ---- scores: S = Q @ K^T (warp tile 32x16) ----
        float sc[2][2][4] = {};
        #pragma unroll 4
        for (int d = 0; d < 128; d += 8) {
            uint32_t a0[4], a1[4], bb[4];
            ldsm4(a0, qA + d * 4);
            ldsm4(a1, qA + (16 * 132 + d) * 4);
            ldsm4(bb, kB + d * 4);
            mma_tf32(sc[0][0], a0, &bb[0]); mma_tf32(sc[0][1], a0, &bb[2]);
            mma_tf32(sc[1][0], a1, &bb[0]); mma_tf32(sc[1][1], a1, &bb[2]);
        }
        #pragma unroll
        for (int i = 0; i < 2; i++)
            #pragma unroll
            for (int j = 0; j < 2; j++) {
                int r0 = sw_m + i * 16 + g;
                int c0 = sw_n + j * 8 + 2 * t;
                float2 s0 = { sc[i][j][0] * scale, sc[i][j][1] * scale };
                float2 s1 = { sc[i][j][2] * scale, sc[i][j][3] * scale };
                *(float2*)&Ss[r0 * 68 + c0] = s0;
                *(float2*)&Ss[(r0 + 8) * 68 + c0] = s1;
            }
        __syncthreads();

        if (kc + 1 < 32) loadK(kc + 1);
        CP_COMMIT();

        // ---- online softmax: warp w -> rows w*8..w*8+7 ----
        {
            int rl = lane >> 2, q = lane & 3;
            int r = w * 8 + rl;
            float* row = &Ss[r * 68];
            float mc = -1e30f;
            #pragma unroll
            for (int cix = 0; cix < 16; cix++) mc = fmaxf(mc, row[q * 16 + cix]);
            mc = fmaxf(mc, __shfl_xor_sync(0xffffffffu, mc, 1));
            mc = fmaxf(mc, __shfl_xor_sync(0xffffffffu, mc, 2));
            float mold = msm[r];
            float mn = fmaxf(mold, mc);
            float al = __expf(mold - mn);
            float ls = 0.0f;
            #pragma unroll
            for (int cix = 0; cix < 16; cix++) {
                float p = __expf(row[q * 16 + cix] - mn);
                ls += p;
                row[q * 16 + cix] = f2tf(p);
            }
            ls += __shfl_xor_sync(0xffffffffu, ls, 1);
            ls += __shfl_xor_sync(0xffffffffu, ls, 2);
            if (q == 0) {
                msm[r] = mn;
                lsm[r] = lsm[r] * al + ls;
                alsm[r] = al;
            }
        }
        CP_WAIT1();
        __syncthreads();

        // ---- PV: O += P @ V (warp tile 32x64) ----
        float aA0 = alsm[pv_m + g],      aB0 = alsm[pv_m + g + 8];
        float aA1 = alsm[pv_m + 16 + g], aB1 = alsm[pv_m + 24 + g];
        #pragma unroll
        for (int j = 0; j < 8; j++) {
            oc[0][j][0] *= aA0; oc[0][j][1] *= aA0;
            oc[0][j][2] *= aB0; oc[0][j][3] *= aB0;
            oc[1][j][0] *= aA1; oc[1][j][1] *= aA1;
            oc[1][j][2] *= aB1; oc[1][j][3] *= aB1;
        }
        #pragma unroll
        for (int ks = 0; ks < 64; ks += 8) {
            uint32_t a0[4], a1[4];
            ldsm4(a0, pA + ks * 4);
            ldsm4(a1, pA + (16 * 68 + ks) * 4);
            #pragma unroll
            for (int jj = 0; jj < 4; jj++) {
                uint32_t bb[4];
                ldsm4(bb, vB + (jj * 16 * 68 + ks) * 4);
                mma_tf32(oc[0][jj * 2],     a0, &bb[0]);
                mma_tf32(oc[0][jj * 2 + 1], a0, &bb[2]);
                mma_tf32(oc[1][jj * 2],     a1, &bb[0]);
                mma_tf32(oc[1][jj * 2 + 1], a1, &bb[2]);
            }
        }
        __syncthreads();
        if (kc + 1 < 32) loadV(kc + 1);
        CP_COMMIT();
    }

    // epilogue
    int b = bh >> 3, h = bh & 7;
    #pragma unroll
    for (int i = 0; i < 2; i++) {
        int rowA = q0 + pv_m + i * 16 + g;
        int rowB = rowA + 8;
        float invA = 1.0f / lsm[pv_m + i * 16 + g];
        float invB = 1.0f / lsm[pv_m + i * 16 + g + 8];
        #pragma unroll
        for (int j = 0; j < 8; j++) {
            int col = h * 256 + pv_n + j * 8 + 2 * t;
            float2 oA = { oc[i][j][0] * invA, oc[i][j][1] * invA };
            float2 oB = { oc[i][j][2] * invB, oc[i][j][3] * invB };
            *(float2*)&O[((size_t)(b * 2048 + rowA)) * 2048 + col] = oA;
            *(float2*)&O[((size_t)(b * 2048 + rowB)) * 2048 + col] = oB;
        }
    }
}

// ---------------- launch ----------------
extern "C" void kernel_launch(void* const* d_in, const int* in_sizes, int n_in,
                              void* d_out, int out_size)
{
    const float* x         = (const float*)d_in[0];
    const int*   pos       = (const int*)d_in[1];
    const float* w_dq_w    = (const float*)d_in[2];
    const float* w_dq_b    = (const float*)d_in[3];
    const float* q_norm_w  = (const float*)d_in[4];
    const float* w_uq_qr_w = (const float*)d_in[5];
    const float* w_uq_qr_b = (const float*)d_in[6];
    const float* w_dkv_w   = (const float*)d_in[7];
    const float* w_dkv_b   = (const float*)d_in[8];
    const float* kv_norm_w = (const float*)d_in[9];
    const float* w_uk_w    = (const float*)d_in[10];
    const float* w_uk_b    = (const float*)d_in[11];
    const float* w_o_w     = (const float*)d_in[12];
    const float* w_o_b     = (const float*)d_in[13];
    float* out = (float*)d_out;

    float *dq, *dkv, *cq, *ckv, *kr, *qraw, *kvraw, *gq, *gk, *gvt, *gattn;
    cudaGetSymbolAddress((void**)&dq, g_dq);
    cudaGetSymbolAddress((void**)&dkv, g_dkv);
    cudaGetSymbolAddress((void**)&cq, g_cq);
    cudaGetSymbolAddress((void**)&ckv, g_ckv);
    cudaGetSymbolAddress((void**)&kr, g_krope);
    cudaGetSymbolAddress((void**)&qraw, g_qraw);
    cudaGetSymbolAddress((void**)&kvraw, g_kvraw);
    cudaGetSymbolAddress((void**)&gq, g_q);
    cudaGetSymbolAddress((void**)&gk, g_k);
    cudaGetSymbolAddress((void**)&gvt, g_vt);
    cudaGetSymbolAddress((void**)&gattn, g_attn);

    cudaFuncSetAttribute(flash_tc, cudaFuncAttributeMaxDynamicSharedMemorySize,
                         FA3_BYTES);

    // down projections
    sgemm_db<128><<<dim3(1, 32), 256>>>(x, w_dq_w, w_dq_b, dq, T_TOK, QC, DIMM);
    sgemm_db<64><<<dim3(3, 32), 256>>>(x, w_dkv_w, w_dkv_b, dkv,
                                       T_TOK, KVC + KROPE, DIMM);
    // rmsnorm + k rope
    norm_rope_kernel<<<T_TOK, 128>>>(dq, dkv, q_norm_w, kv_norm_w, pos, cq, ckv, kr);
    // up projections
    sgemm_db<128><<<dim3(8, 32), 256>>>(cq, w_uq_qr_w, w_uq_qr_b, qraw,
                                        T_TOK, 1024, QC);
    sgemm_db<128><<<dim3(20, 32), 256>>>(ckv, w_uk_w, w_uk_b, kvraw,
                                         T_TOK, 2560, KVC);
    // build per-head states
    scatter_qk<<<T_TOK, 256>>>(qraw, kvraw, kr, pos, gq, gk);
    v_transpose<<<dim3(16, 64, 8), 256>>>(kvraw, gvt);
    // attention
    flash_tc<<<dim3(S_LEN / 128, 16), 512, FA3_BYTES>>>(gq, gk, gvt, gattn);
    // output projection
    sgemm_db<128><<<dim3(8, 32), 256>>>(gattn, w_o_w, w_o_b, out,
                                        T_TOK, DIMM, 2048);
}